// round 4
// baseline (speedup 1.0000x reference)
#include <cuda_runtime.h>
#include <cuda_bf16.h>
#include <cstdint>

#define GROUPS 4
#define KCODES 1024
#define DIM 64
#define TOK 128
#define CT 64                 // codes per tile
#define NT (KCODES / CT)      // 16 tiles

typedef unsigned long long u64t;

__device__ double g_loss_acc;
__device__ float  g_csq[GROUPS * KCODES];
__device__ __align__(16) __nv_bfloat16 g_yh[GROUPS * KCODES * DIM];  // bf16(-2c) hi
__device__ __align__(16) __nv_bfloat16 g_yl[GROUPS * KCODES * DIM];  // bf16 residual

// ---------------- helpers ----------------
__device__ __forceinline__ uint32_t smem_u32(const void* p) {
    uint32_t a;
    asm("{ .reg .u64 t; cvta.to.shared.u64 t, %1; cvt.u32.u64 %0, t; }" : "=r"(a) : "l"(p));
    return a;
}
__device__ __forceinline__ void ldsm4(uint32_t& r0, uint32_t& r1, uint32_t& r2, uint32_t& r3,
                                      uint32_t addr) {
    asm volatile("ldmatrix.sync.aligned.m8n8.x4.shared.b16 {%0,%1,%2,%3}, [%4];"
                 : "=r"(r0), "=r"(r1), "=r"(r2), "=r"(r3) : "r"(addr));
}
__device__ __forceinline__ void mma_bf16(float* d, const uint32_t* a, uint32_t b0, uint32_t b1) {
    asm volatile("mma.sync.aligned.m16n8k16.row.col.f32.bf16.bf16.f32 "
                 "{%0,%1,%2,%3}, {%4,%5,%6,%7}, {%8,%9}, {%0,%1,%2,%3};"
                 : "+f"(d[0]), "+f"(d[1]), "+f"(d[2]), "+f"(d[3])
                 : "r"(a[0]), "r"(a[1]), "r"(a[2]), "r"(a[3]), "r"(b0), "r"(b1));
}
__device__ __forceinline__ void cpasync16(uint32_t dst, const void* src) {
    asm volatile("cp.async.cg.shared.global [%0], [%1], 16;" :: "r"(dst), "l"(src));
}
#define CP_COMMIT() asm volatile("cp.async.commit_group;")
#define CP_WAIT0()  asm volatile("cp.async.wait_group 0;")
#define CP_WAIT1()  asm volatile("cp.async.wait_group 1;")

__device__ __forceinline__ u64t pack2(float a, float b) {
    u64t r; asm("mov.b64 %0, {%1, %2};" : "=l"(r) : "f"(a), "f"(b)); return r;
}
__device__ __forceinline__ void unpack2(u64t p, float& a, float& b) {
    asm("mov.b64 {%0, %1}, %2;" : "=f"(a), "=f"(b) : "l"(p));
}
__device__ __forceinline__ u64t fma2(u64t a, u64t b, u64t c) {
    u64t d; asm("fma.rn.f32x2 %0, %1, %2, %3;" : "=l"(d) : "l"(a), "l"(b), "l"(c)); return d;
}

// ---------------- prep: loss=0, exact csq, bf16-split y=-2c ----------------
__global__ void vq_prep_kernel(const float* __restrict__ cb) {
    int idx = blockIdx.x * blockDim.x + threadIdx.x;
    if (idx == 0) g_loss_acc = 0.0;
    if (idx < GROUPS * KCODES) {
        const float4* p = (const float4*)(cb + (size_t)idx * DIM);
        float s = 0.f;
#pragma unroll
        for (int i = 0; i < DIM / 4; i++) {
            float4 v = p[i];
            s = __fadd_rn(s, __fmul_rn(v.x, v.x));
            s = __fadd_rn(s, __fmul_rn(v.y, v.y));
            s = __fadd_rn(s, __fmul_rn(v.z, v.z));
            s = __fadd_rn(s, __fmul_rn(v.w, v.w));
        }
        g_csq[idx] = s;
    }
    if (idx < GROUPS * KCODES * 16) {      // one thread per (g,k,quad of 4 dims)
        int q = idx & 15, k = (idx >> 4) & (KCODES - 1), g = idx >> 14;
        float4 c = *(const float4*)(cb + ((size_t)g * KCODES + k) * DIM + 4 * q);
        float y0 = -2.f * c.x, y1 = -2.f * c.y, y2 = -2.f * c.z, y3 = -2.f * c.w;
        __nv_bfloat16 h0 = __float2bfloat16(y0), h1 = __float2bfloat16(y1);
        __nv_bfloat16 h2 = __float2bfloat16(y2), h3 = __float2bfloat16(y3);
        __nv_bfloat16 e0 = __float2bfloat16(y0 - __bfloat162float(h0));
        __nv_bfloat16 e1 = __float2bfloat16(y1 - __bfloat162float(h1));
        __nv_bfloat16 e2 = __float2bfloat16(y2 - __bfloat162float(h2));
        __nv_bfloat16 e3 = __float2bfloat16(y3 - __bfloat162float(h3));
        size_t off = ((size_t)(g * KCODES + k)) * DIM + 4 * q;
        uint2 ph, pl;
        ph.x = ((uint32_t)__bfloat16_as_ushort(h1) << 16) | __bfloat16_as_ushort(h0);
        ph.y = ((uint32_t)__bfloat16_as_ushort(h3) << 16) | __bfloat16_as_ushort(h2);
        pl.x = ((uint32_t)__bfloat16_as_ushort(e1) << 16) | __bfloat16_as_ushort(e0);
        pl.y = ((uint32_t)__bfloat16_as_ushort(e3) << 16) | __bfloat16_as_ushort(e2);
        *(uint2*)((char*)g_yh + off * 2) = ph;
        *(uint2*)((char*)g_yl + off * 2) = pl;
    }
}

// ---------------- smem layout (bytes) ----------------
#define ROWB     144          // 72 bf16 per row (64 data + 8 pad) -> ldmatrix conflict-free
#define SM_X     0            // Xh[128][72], Xl at +18432  (36864)
#define SM_C     36864        // 2 buffers x (Ch[64][72]=9216 + Cl=9216)  (36864)
#define SM_CSQ   73728        // 1024 f
#define SM_XSQ   77824        // 128 f
#define SM_MARG  78336        // 128 f
#define SM_IDX   78848        // 128 int
#define SM_UCNT  79360
#define SM_KEY   79368
#define SM_ULIST 79376        // 128 int
#define SM_URES  79888        // 128 int
#define SM_SRED  80400        // 8 dbl
#define SMEM_BYTES 80464

__global__ void __launch_bounds__(256, 2)
vq_main_kernel(const float* __restrict__ lat, const float* __restrict__ cb,
               float* __restrict__ out, int ntok) {
    extern __shared__ char smem[];
    const uint32_t sb = smem_u32(smem);
    const int tid = threadIdx.x;
    const int w   = tid >> 5;
    const int l   = tid & 31;
    const int b   = blockIdx.x;
    const int g   = b & 3;
    const int tok0 = (b >> 2) * TOK;

    const float* latg = lat + (size_t)g * DIM;
    const float* cbg  = cb + (size_t)g * KCODES * DIM;
    float* csq_s  = (float*)(smem + SM_CSQ);
    float* xsq_s  = (float*)(smem + SM_XSQ);
    float* marg_s = (float*)(smem + SM_MARG);
    int*   idx_s  = (int*)(smem + SM_IDX);

    if (tid == 0) *(int*)(smem + SM_UCNT) = 0;

    // ---- stage X: bf16 hi/lo into [tok][72] rows
#pragma unroll
    for (int it = 0; it < 8; it++) {
        int i = tid + 256 * it;
        int r = i >> 4, q = i & 15;
        int tok = tok0 + r; if (tok >= ntok) tok = ntok - 1;
        float4 v = *(const float4*)(latg + (size_t)tok * (GROUPS * DIM) + 4 * q);
        __nv_bfloat16 h0 = __float2bfloat16(v.x), h1 = __float2bfloat16(v.y);
        __nv_bfloat16 h2 = __float2bfloat16(v.z), h3 = __float2bfloat16(v.w);
        __nv_bfloat16 e0 = __float2bfloat16(v.x - __bfloat162float(h0));
        __nv_bfloat16 e1 = __float2bfloat16(v.y - __bfloat162float(h1));
        __nv_bfloat16 e2 = __float2bfloat16(v.z - __bfloat162float(h2));
        __nv_bfloat16 e3 = __float2bfloat16(v.w - __bfloat162float(h3));
        uint2 ph, pl;
        ph.x = ((uint32_t)__bfloat16_as_ushort(h1) << 16) | __bfloat16_as_ushort(h0);
        ph.y = ((uint32_t)__bfloat16_as_ushort(h3) << 16) | __bfloat16_as_ushort(h2);
        pl.x = ((uint32_t)__bfloat16_as_ushort(e1) << 16) | __bfloat16_as_ushort(e0);
        pl.y = ((uint32_t)__bfloat16_as_ushort(e3) << 16) | __bfloat16_as_ushort(e2);
        *(uint2*)(smem + SM_X + r * ROWB + q * 8) = ph;
        *(uint2*)(smem + SM_X + 18432 + r * ROWB + q * 8) = pl;
    }
    // ---- xsq (exact reference rounding) + margin
    if (tid < TOK) {
        int tok = tok0 + tid; if (tok >= ntok) tok = ntok - 1;
        const float4* xg = (const float4*)(latg + (size_t)tok * (GROUPS * DIM));
        float s = 0.f, sx = 0.f;
#pragma unroll
        for (int i = 0; i < DIM / 4; i++) {
            float4 v = xg[i];
            s = __fadd_rn(s, __fmul_rn(v.x, v.x));
            s = __fadd_rn(s, __fmul_rn(v.y, v.y));
            s = __fadd_rn(s, __fmul_rn(v.z, v.z));
            s = __fadd_rn(s, __fmul_rn(v.w, v.w));
            sx += fabsf(v.x) + fabsf(v.y) + fabsf(v.z) + fabsf(v.w);
        }
        xsq_s[tid] = s;
        float P = 1.953125e-3f * sx;               // bound on sum |x||y|
        marg_s[tid] = 4e-4f * P + 7.2e-7f * s + 2e-6f;
    }
#pragma unroll
    for (int r = 0; r < 4; r++) csq_s[tid + 256 * r] = g_csq[g * KCODES + tid + 256 * r];

    // ---- cp.async codebook tile 0
    {
        const char* srch = (const char*)g_yh + ((size_t)(g * KCODES) * DIM) * 2;
        const char* srcl = (const char*)g_yl + ((size_t)(g * KCODES) * DIM) * 2;
#pragma unroll
        for (int cch = 0; cch < 2; cch++) {
            int c = 2 * tid + cch;                 // 0..511
            int code = c >> 3, k8 = c & 7;
            uint32_t dst = sb + SM_C + code * ROWB + k8 * 16;
            cpasync16(dst, srch + ((size_t)code * DIM + k8 * 8) * 2);
            cpasync16(dst + 9216, srcl + ((size_t)code * DIM + k8 * 8) * 2);
        }
        CP_COMMIT();
    }
    __syncthreads();

    // ---- A fragments (register resident): Ah/Al[4 ksteps][4]
    uint32_t Ah[4][4], Al[4][4];
    {
        uint32_t xrow = (uint32_t)(w * 16 + (l & 15));
        uint32_t xcol = ((l >> 4) << 3);
#pragma unroll
        for (int kk = 0; kk < 4; kk++) {
            uint32_t ad = sb + SM_X + xrow * ROWB + (kk * 16 + xcol) * 2;
            ldsm4(Ah[kk][0], Ah[kk][1], Ah[kk][2], Ah[kk][3], ad);
            ldsm4(Al[kk][0], Al[kk][1], Al[kk][2], Al[kk][3], ad + 18432);
        }
    }

    const int t_ = l & 3, gq = l >> 2;
    float m1L = 3.4e38f, m2L = 3.4e38f, m1H = 3.4e38f, m2H = 3.4e38f;
    int   i1L = 0, i1H = 0;
    const uint32_t crow = (uint32_t)((l & 7) + ((l >> 4) << 3));
    const uint32_t ccol = (uint32_t)(l & 8);

    for (int t = 0; t < NT; t++) {
        if (t + 1 < NT) {                          // async copy next tile
            const char* srch = (const char*)g_yh + ((size_t)(g * KCODES + (t + 1) * CT) * DIM) * 2;
            const char* srcl = (const char*)g_yl + ((size_t)(g * KCODES + (t + 1) * CT) * DIM) * 2;
            uint32_t nb = sb + SM_C + ((t + 1) & 1) * 18432;
#pragma unroll
            for (int cch = 0; cch < 2; cch++) {
                int c = 2 * tid + cch;
                int code = c >> 3, k8 = c & 7;
                cpasync16(nb + code * ROWB + k8 * 16, srch + ((size_t)code * DIM + k8 * 8) * 2);
                cpasync16(nb + 9216 + code * ROWB + k8 * 16, srcl + ((size_t)code * DIM + k8 * 8) * 2);
            }
            CP_COMMIT();
            CP_WAIT1();                            // tile t landed
        } else {
            CP_WAIT0();
        }
        __syncthreads();                           // tile t visible to all

        const uint32_t cbh = sb + SM_C + (t & 1) * 18432;
        float D[8][4];
#pragma unroll
        for (int nf = 0; nf < 8; nf++) { D[nf][0] = D[nf][1] = D[nf][2] = D[nf][3] = 0.f; }

#pragma unroll
        for (int kk = 0; kk < 4; kk++) {
#pragma unroll
            for (int nfp = 0; nfp < 4; nfp++) {
                uint32_t ba = cbh + (nfp * 16 + crow) * ROWB + (kk * 16 + ccol) * 2;
                uint32_t b0, b1, b2, b3;
                ldsm4(b0, b1, b2, b3, ba);                     // Bh: 2 n-frags
                mma_bf16(D[2 * nfp],     Ah[kk], b0, b1);
                mma_bf16(D[2 * nfp],     Al[kk], b0, b1);
                mma_bf16(D[2 * nfp + 1], Ah[kk], b2, b3);
                mma_bf16(D[2 * nfp + 1], Al[kk], b2, b3);
                ldsm4(b0, b1, b2, b3, ba + 9216);              // Bl
                mma_bf16(D[2 * nfp],     Ah[kk], b0, b1);
                mma_bf16(D[2 * nfp + 1], Ah[kk], b2, b3);
            }
        }

        // ---- scan this tile's scores (codes ascending within lane)
#pragma unroll
        for (int nf = 0; nf < 8; nf++) {
            int c0 = t * CT + nf * 8 + 2 * t_;
            float q0 = csq_s[c0], q1 = csq_s[c0 + 1];
            float s0 = D[nf][0] + q0, s1 = D[nf][1] + q1;
            float s2 = D[nf][2] + q0, s3 = D[nf][3] + q1;
            if (s0 < m2L) { if (s0 < m1L) { m2L = m1L; m1L = s0; i1L = c0; } else m2L = s0; }
            if (s1 < m2L) { if (s1 < m1L) { m2L = m1L; m1L = s1; i1L = c0 + 1; } else m2L = s1; }
            if (s2 < m2H) { if (s2 < m1H) { m2H = m1H; m1H = s2; i1H = c0; } else m2H = s2; }
            if (s3 < m2H) { if (s3 < m1H) { m2H = m1H; m1H = s3; i1H = c0 + 1; } else m2H = s3; }
        }
        __syncthreads();                           // readers done before next STS overwrite
    }

    // ---- merge min1/min2/idx across the 4 lanes of each quad
#pragma unroll
    for (int d = 1; d <= 2; d <<= 1) {
        float om1 = __shfl_xor_sync(0xFFFFFFFFu, m1L, d);
        float om2 = __shfl_xor_sync(0xFFFFFFFFu, m2L, d);
        int   oi  = __shfl_xor_sync(0xFFFFFFFFu, i1L, d);
        float nm2 = fminf(fmaxf(m1L, om1), fminf(m2L, om2));
        if (om1 < m1L || (om1 == m1L && oi < i1L)) { m1L = om1; i1L = oi; }
        m2L = nm2;
        om1 = __shfl_xor_sync(0xFFFFFFFFu, m1H, d);
        om2 = __shfl_xor_sync(0xFFFFFFFFu, m2H, d);
        oi  = __shfl_xor_sync(0xFFFFFFFFu, i1H, d);
        nm2 = fminf(fmaxf(m1H, om1), fminf(m2H, om2));
        if (om1 < m1H || (om1 == m1H && oi < i1H)) { m1H = om1; i1H = oi; }
        m2H = nm2;
    }
    if (t_ == 0) {
        int tokL = w * 16 + gq, tokH = tokL + 8;
        idx_s[tokL] = i1L;
        idx_s[tokH] = i1H;
        if (tok0 + tokL < ntok && (m2L - m1L) < marg_s[tokL]) {
            int pos = atomicAdd((int*)(smem + SM_UCNT), 1);
            ((int*)(smem + SM_ULIST))[pos] = tokL;
        }
        if (tok0 + tokH < ntok && (m2H - m1H) < marg_s[tokH]) {
            int pos = atomicAdd((int*)(smem + SM_UCNT), 1);
            ((int*)(smem + SM_ULIST))[pos] = tokH;
        }
    }
    __syncthreads();
    const int ucnt = *(const int*)(smem + SM_UCNT);

    // ---- exact fallback (bitwise R1 arithmetic) for uncertain tokens
    for (int e = 0; e < ucnt; e++) {
        int ut = ((const int*)(smem + SM_ULIST))[e];
        if (tid == 0) *(u64t*)(smem + SM_KEY) = ~0ull;
        __syncthreads();
        int tok = tok0 + ut;
        const float4* xg = (const float4*)(latg + (size_t)tok * (GROUPS * DIM));
        u64t xp[DIM / 2];
#pragma unroll
        for (int i = 0; i < DIM / 4; i++) {
            float4 v = xg[i];
            xp[2 * i] = pack2(v.x, v.y); xp[2 * i + 1] = pack2(v.z, v.w);
        }
        float xsq_t = xsq_s[ut];
        u64t lkey = ~0ull;
#pragma unroll
        for (int c = 0; c < 4; c++) {
            int k = tid * 4 + c;
            const float4* cr = (const float4*)(cbg + (size_t)k * DIM);
            u64t a0 = 0, a1 = 0, a2 = 0, a3 = 0;
#pragma unroll
            for (int j2 = 0; j2 < 8; j2++) {
                float4 cA = cr[2 * j2], cB = cr[2 * j2 + 1];
                a0 = fma2(xp[4 * j2 + 0], pack2(cA.x, cA.y), a0);
                a1 = fma2(xp[4 * j2 + 1], pack2(cA.z, cA.w), a1);
                a2 = fma2(xp[4 * j2 + 2], pack2(cB.x, cB.y), a2);
                a3 = fma2(xp[4 * j2 + 3], pack2(cB.z, cB.w), a3);
            }
            float f0, f1, f2, f3, f4, f5, f6, f7;
            unpack2(a0, f0, f1); unpack2(a1, f2, f3);
            unpack2(a2, f4, f5); unpack2(a3, f6, f7);
            float dot = ((f0 + f2) + (f4 + f6)) + ((f1 + f3) + (f5 + f7));
            float dist = __fadd_rn(__fsub_rn(xsq_t, __fmul_rn(2.f, dot)), csq_s[k]);
            u64t key = ((u64t)__float_as_uint(dist) << 32) | (unsigned)k;
            if (key < lkey) lkey = key;
        }
        atomicMin((u64t*)(smem + SM_KEY), lkey);
        __syncthreads();
        if (tid == 0) ((int*)(smem + SM_URES))[e] = (int)(*(u64t*)(smem + SM_KEY) & 0xFFFFFFFFu);
        __syncthreads();
    }
    int my_bi = 0;
    bool valid = false;
    if (tid < TOK) {
        my_bi = idx_s[tid];
        valid = (tok0 + tid < ntok);
        for (int e = 0; e < ucnt; e++)
            if (((const int*)(smem + SM_ULIST))[e] == tid)
                my_bi = ((const int*)(smem + SM_URES))[e];
    }
    __syncthreads();     // X region reused as output staging below

    // ---- gather winner, out = x + (q - x), loss accumulation
    float4* stage = (float4*)(smem + SM_X);
    float lsum = 0.f;
    if (tid < TOK && valid) {
        int tok = tok0 + tid;
        const float4* cq = (const float4*)(cbg + (size_t)my_bi * DIM);
        const float4* xg = (const float4*)(latg + (size_t)tok * (GROUPS * DIM));
#pragma unroll
        for (int i = 0; i < DIM / 4; i++) {
            int f = (i + tid) & 15;
            float4 xv = xg[f];
            float4 cv = cq[f];
            float4 o; float t2;
            t2 = __fsub_rn(cv.x, xv.x); o.x = __fadd_rn(xv.x, t2); lsum = __fmaf_rn(t2, t2, lsum);
            t2 = __fsub_rn(cv.y, xv.y); o.y = __fadd_rn(xv.y, t2); lsum = __fmaf_rn(t2, t2, lsum);
            t2 = __fsub_rn(cv.z, xv.z); o.z = __fadd_rn(xv.z, t2); lsum = __fmaf_rn(t2, t2, lsum);
            t2 = __fsub_rn(cv.w, xv.w); o.w = __fadd_rn(xv.w, t2); lsum = __fmaf_rn(t2, t2, lsum);
            stage[tid * 16 + f] = o;
        }
    }
#pragma unroll
    for (int off = 16; off; off >>= 1)
        lsum += __shfl_xor_sync(0xFFFFFFFFu, lsum, off);
    if (l == 0) ((double*)(smem + SM_SRED))[w] = (double)lsum;
    __syncthreads();
    if (tid == 0) {
        double acc = 0.0;
#pragma unroll
        for (int i = 0; i < 8; i++) acc += ((const double*)(smem + SM_SRED))[i];
        atomicAdd(&g_loss_acc, acc);
    }
    {
        const float4* st = (const float4*)(smem + SM_X);
#pragma unroll
        for (int r = 0; r < 8; r++) {
            int li = tid + r * 256;
            int tt = li >> 4, f = li & 15;
            int tok = tok0 + tt;
            if (tok < ntok)
                *(float4*)(out + (size_t)tok * (GROUPS * DIM) + g * DIM + 4 * f) = st[li];
        }
    }
}

__global__ void vq_finish_kernel(float* __restrict__ out, long long loss_idx,
                                 long long count) {
    double m = g_loss_acc / (double)count;
    float mf = (float)m;
    out[loss_idx] = __fadd_rn(__fmul_rn(mf, 0.25f), mf);
}

extern "C" void kernel_launch(void* const* d_in, const int* in_sizes, int n_in,
                              void* d_out, int out_size) {
    const float* lat = (const float*)d_in[0];
    const float* cb  = (const float*)d_in[1];
    float* out = (float*)d_out;

    const int n_lat = in_sizes[0];
    const int ntok  = n_lat / (GROUPS * DIM);

    cudaFuncSetAttribute(vq_main_kernel,
                         cudaFuncAttributeMaxDynamicSharedMemorySize, SMEM_BYTES);

    vq_prep_kernel<<<(GROUPS * KCODES * 16 + 255) / 256, 256>>>(cb);

    int tokBlocks = (ntok + TOK - 1) / TOK;
    vq_main_kernel<<<tokBlocks * GROUPS, 256, SMEM_BYTES>>>(lat, cb, out, ntok);

    vq_finish_kernel<<<1, 1>>>(out, (long long)out_size - 1, (long long)n_lat);
}